// round 11
// baseline (speedup 1.0000x reference)
#include <cuda_runtime.h>
#include <cuda_fp16.h>
#include <cstdint>

// Problem constants (fixed by dataset)
#define N_NODES 50000
#define N_EDGES 800000
#define F_IN   128
#define F_H1   256
#define F_H    128
#define F_OUT  32
#define M_PAD  50048   // 391 * 128

// ---------------- scratch (static device globals) ---------------------------
__device__ int   g_count [N_NODES];
__device__ float g_dinv  [M_PAD];        // pad rows stay 0
__device__ int   g_rowptr[N_NODES + 1];
__device__ int   g_cursor[N_NODES];
__device__ int   g_col   [N_EDGES];
__device__ int   g_pfx   [64];           // chained-scan prefix (+1; 0 = not ready)

// fp16 activations
__device__ __half g_x16[(size_t)N_NODES * F_IN];   // dinv-prescaled fp16 x
__device__ __half g_a1 [(size_t)M_PAD * F_IN];     // agg1 out (GEMM1 A); pad rows stay 0
__device__ __half g_h1 [(size_t)M_PAD * F_H1];
__device__ __half g_g2 [(size_t)M_PAD * F_H];
__device__ __half g_h2 [(size_t)M_PAD * F_H];
__device__ __half g_g3 [(size_t)M_PAD * F_OUT];
// transposed fp16 weights [N][K] (K-major rows)
__device__ __half g_w1[256 * 128];
__device__ __half g_w2[128 * 256];
__device__ __half g_w3[32 * 128];

// ---------------- PTX helpers ------------------------------------------------
__device__ __forceinline__ uint32_t smem_u32(const void* p) {
    uint32_t a;
    asm("{ .reg .u64 t; cvta.to.shared.u64 t, %1; cvt.u32.u64 %0, t; }"
        : "=r"(a) : "l"(p));
    return a;
}
__device__ __forceinline__ void ldsm4(uint32_t addr, uint32_t r[4]) {
    asm volatile("ldmatrix.sync.aligned.m8n8.x4.shared.b16 {%0,%1,%2,%3}, [%4];"
                 : "=r"(r[0]), "=r"(r[1]), "=r"(r[2]), "=r"(r[3]) : "r"(addr));
}
__device__ __forceinline__ void ldsm2(uint32_t addr, uint32_t r[2]) {
    asm volatile("ldmatrix.sync.aligned.m8n8.x2.shared.b16 {%0,%1}, [%2];"
                 : "=r"(r[0]), "=r"(r[1]) : "r"(addr));
}
__device__ __forceinline__ void mma16816h(float* c, const uint32_t* a, const uint32_t* b) {
    asm volatile(
        "mma.sync.aligned.m16n8k16.row.col.f32.f16.f16.f32 "
        "{%0,%1,%2,%3}, {%4,%5,%6,%7}, {%8,%9}, {%0,%1,%2,%3};"
        : "+f"(c[0]), "+f"(c[1]), "+f"(c[2]), "+f"(c[3])
        : "r"(a[0]), "r"(a[1]), "r"(a[2]), "r"(a[3]), "r"(b[0]), "r"(b[1]));
}
__device__ __forceinline__ void cp16(uint32_t saddr, const void* gaddr) {
    asm volatile("cp.async.cg.shared.global [%0], [%1], 16;"
                 :: "r"(saddr), "l"(gaddr));
}
#define CP_COMMIT() asm volatile("cp.async.commit_group;" ::: "memory")

// ---------------- launch 1: fused prep (degree + W transpose + flags) -------
__global__ __launch_bounds__(256)
void prep_kernel(const int* __restrict__ ei,
                 const float* __restrict__ W1, const float* __restrict__ W2,
                 const float* __restrict__ W3,
                 __half* w1, __half* w2, __half* w3,
                 int e, int B_deg, int B_w) {
    int bid = blockIdx.x, tid = threadIdx.x;
    if (bid < B_deg) {                                   // degree atomics
        int i = bid * 256 + tid;
        if (i < e) atomicAdd(&g_count[ei[e + i]], 1);
    } else if (bid < B_deg + B_w) {                      // weight transpose (fp16)
        int idx = (bid - B_deg) * 256 + tid;
        if (idx < 32768) {                               // W1 [128,256] -> [256][128]
            int nn = idx / 128, k = idx % 128;
            w1[idx] = __float2half(W1[k * 256 + nn]);
        } else if (idx < 65536) {                        // W2 [256,128] -> [128][256]
            int i2 = idx - 32768;
            int nn = i2 / 256, k = i2 % 256;
            w2[i2] = __float2half(W2[k * 128 + nn]);
        } else if (idx < 65536 + 4096) {                 // W3 [128,32] -> [32][128]
            int i3 = idx - 65536;
            int nn = i3 / 128, k = i3 % 128;
            w3[i3] = __float2half(W3[k * 32 + nn]);
        }
    } else {                                             // zero scan flags
        if (tid < 64) g_pfx[tid] = 0;
    }
}

// ---------------- launch 2: chained single-pass scan -------------------------
__global__ __launch_bounds__(1024)
void scan_chained_kernel(int n, int nb) {
    __shared__ int temp[1024];
    __shared__ int pfx_sh;
    int bid = blockIdx.x, tid = threadIdx.x;
    int i = bid * 1024 + tid;
    int v = (i < n) ? g_count[i] : 0;
    if (i < n) {
        g_dinv[i]  = rsqrtf((float)(v + 1));   // +1 self-loop
        g_count[i] = 0;                        // reset for next replay
    }
    temp[tid] = v;
    __syncthreads();
    #pragma unroll
    for (int off = 1; off < 1024; off <<= 1) {
        int t = (tid >= off) ? temp[tid - off] : 0;
        __syncthreads();
        temp[tid] += t;
        __syncthreads();
    }
    if (tid == 0) {
        int p = 0;
        if (bid > 0) {
            while ((p = atomicAdd(&g_pfx[bid - 1], 0)) == 0) __nanosleep(20);
            p -= 1;
        }
        atomicExch(&g_pfx[bid], p + temp[1023] + 1);
        pfx_sh = p;
    }
    __syncthreads();
    int base = pfx_sh;
    if (i < n) {
        int excl = base + temp[tid] - v;
        g_rowptr[i] = excl;
        g_cursor[i] = excl;
    }
    if (bid == nb - 1 && tid == 1023) g_rowptr[n] = base + temp[1023];
}

// ---------------- launch 3: x fp32 -> dinv-prescaled fp16 (single pass) -----
__global__ __launch_bounds__(256)
void conv_kernel(const float* __restrict__ x, __half* __restrict__ x16, int n) {
    int i = blockIdx.x * blockDim.x + threadIdx.x;
    int node = i >> 4, lane = i & 15;
    if (node >= n) return;
    float di = g_dinv[node];
    const float4* xv = (const float4*)x;
    float4 a = xv[(size_t)node * 32 + lane * 2];
    float4 b = xv[(size_t)node * 32 + lane * 2 + 1];
    __half2 h0 = __floats2half2_rn(di * a.x, di * a.y);
    __half2 h1 = __floats2half2_rn(di * a.z, di * a.w);
    __half2 h2 = __floats2half2_rn(di * b.x, di * b.y);
    __half2 h3 = __floats2half2_rn(di * b.z, di * b.w);
    uint4 o;
    o.x = *reinterpret_cast<uint32_t*>(&h0);
    o.y = *reinterpret_cast<uint32_t*>(&h1);
    o.z = *reinterpret_cast<uint32_t*>(&h2);
    o.w = *reinterpret_cast<uint32_t*>(&h3);
    *reinterpret_cast<uint4*>(x16 + (size_t)node * F_IN + lane * 8) = o;
}

// ---------------- launch 4: CSR fill ----------------------------------------
__global__ __launch_bounds__(256)
void fill_csr_kernel(const int* __restrict__ ei, int e) {
    int i = blockIdx.x * blockDim.x + threadIdx.x;
    if (i < e) {
        int src = ei[i];
        int dst = ei[e + i];
        int pos = atomicAdd(&g_cursor[dst], 1);
        g_col[pos] = src;
    }
}

// ---------------- fp16 pull aggregation (32B/thread, pairwise hadd2) ---------
__device__ __forceinline__ void add8(float* acc, uint4 v) {
    const __half2* h = reinterpret_cast<const __half2*>(&v);
    #pragma unroll
    for (int q = 0; q < 4; q++) {
        float2 f = __half22float2(h[q]);
        acc[2 * q] += f.x; acc[2 * q + 1] += f.y;
    }
}
__device__ __forceinline__ uint4 hadd2x4(uint4 a, uint4 b) {
    const __half2* pa = reinterpret_cast<const __half2*>(&a);
    const __half2* pb = reinterpret_cast<const __half2*>(&b);
    uint4 r;
    __half2* pr = reinterpret_cast<__half2*>(&r);
    #pragma unroll
    for (int q = 0; q < 4; q++) pr[q] = __hadd2(pa[q], pb[q]);
    return r;
}

// out[d] = dinv[d]*(g[d] + sum g[s]) (+bias)(relu); g rows dinv[src]-prescaled.
// Each thread owns 16 features (32 bytes = 2 uint4) -> TPN = F/16 threads/node.
template <int F, bool BIAS, bool RELU, bool OUT32>
__global__ void agg16_kernel(const __half* __restrict__ g,
                             const float* __restrict__ bias,
                             __half* __restrict__ outh,
                             float* __restrict__ outf, int n) {
    constexpr int TPN = F / 16;
    constexpr uint32_t RB = F * 2;     // row bytes (total < 26MB fits 32-bit)
    int npb  = blockDim.x / TPN;
    int node = blockIdx.x * npb + threadIdx.x / TPN;
    if (node >= n) return;
    int lane = threadIdx.x % TPN;

    const char* base = (const char*)g + lane * 32;
    float acc[16];
    #pragma unroll
    for (int q = 0; q < 16; q++) acc[q] = 0.0f;
    {
        const uint4* p = reinterpret_cast<const uint4*>(base + (uint32_t)node * RB);
        add8(acc, p[0]); add8(acc + 8, p[1]);          // self (prescaled)
    }

    int e  = g_rowptr[node];
    int e1 = g_rowptr[node + 1];
    for (; e + 4 <= e1; e += 4) {
        uint32_t off[4];
        #pragma unroll
        for (int j = 0; j < 4; j++) off[j] = (uint32_t)g_col[e + j] * RB;
        uint4 a[4], b[4];
        #pragma unroll
        for (int j = 0; j < 4; j++) {
            const uint4* p = reinterpret_cast<const uint4*>(base + off[j]);
            a[j] = p[0]; b[j] = p[1];
        }
        uint4 pa0 = hadd2x4(a[0], a[1]), pa1 = hadd2x4(a[2], a[3]);
        uint4 pb0 = hadd2x4(b[0], b[1]), pb1 = hadd2x4(b[2], b[3]);
        add8(acc, pa0); add8(acc, pa1);
        add8(acc + 8, pb0); add8(acc + 8, pb1);
    }
    for (; e < e1; e++) {
        const uint4* p = reinterpret_cast<const uint4*>(base + (uint32_t)g_col[e] * RB);
        add8(acc, p[0]); add8(acc + 8, p[1]);
    }

    float di = g_dinv[node];
    #pragma unroll
    for (int q = 0; q < 16; q++) acc[q] *= di;
    if (BIAS) {
        const float4* bp = (const float4*)(bias + lane * 16);
        #pragma unroll
        for (int q4 = 0; q4 < 4; q4++) {
            float4 b = bp[q4];
            acc[q4 * 4 + 0] += b.x; acc[q4 * 4 + 1] += b.y;
            acc[q4 * 4 + 2] += b.z; acc[q4 * 4 + 3] += b.w;
        }
    }
    if (RELU) {
        #pragma unroll
        for (int q = 0; q < 16; q++) acc[q] = fmaxf(acc[q], 0.0f);
    }
    if constexpr (OUT32) {
        size_t o = (size_t)node * F + lane * 16;
        #pragma unroll
        for (int q4 = 0; q4 < 4; q4++)
            *reinterpret_cast<float4*>(outf + o + q4 * 4) =
                make_float4(acc[q4 * 4], acc[q4 * 4 + 1], acc[q4 * 4 + 2], acc[q4 * 4 + 3]);
    } else {
        uint4 o16[2];
        #pragma unroll
        for (int hlf = 0; hlf < 2; hlf++) {
            __half2 p0 = __floats2half2_rn(acc[hlf * 8 + 0], acc[hlf * 8 + 1]);
            __half2 p1 = __floats2half2_rn(acc[hlf * 8 + 2], acc[hlf * 8 + 3]);
            __half2 p2 = __floats2half2_rn(acc[hlf * 8 + 4], acc[hlf * 8 + 5]);
            __half2 p3 = __floats2half2_rn(acc[hlf * 8 + 6], acc[hlf * 8 + 7]);
            o16[hlf].x = *reinterpret_cast<uint32_t*>(&p0);
            o16[hlf].y = *reinterpret_cast<uint32_t*>(&p1);
            o16[hlf].z = *reinterpret_cast<uint32_t*>(&p2);
            o16[hlf].w = *reinterpret_cast<uint32_t*>(&p3);
        }
        size_t o = (size_t)node * F + lane * 16;
        *reinterpret_cast<uint4*>(outh + o)     = o16[0];
        *reinterpret_cast<uint4*>(outh + o + 8) = o16[1];
    }
}

// ---------------- fp16 GEMM (single W), cp.async 2-stage ---------------------
template <int NB, int K, int WARPS_M, int WARPS_N, bool BIAS, bool RELU, bool DINV>
__global__ __launch_bounds__(32 * WARPS_M * WARPS_N)
void gemm_f16(const __half* __restrict__ A, const __half* __restrict__ W,
              const float* __restrict__ bias,
              __half* __restrict__ C, int M, int Ntotal) {
    constexpr int BM  = 128;
    constexpr int KC  = 32;
    constexpr int LDS = KC + 8;
    constexpr int NT  = 32 * WARPS_M * WARPS_N;
    constexpr int WM  = BM / WARPS_M;
    constexpr int WN  = NB / WARPS_N;
    constexpr int MF  = WM / 16;
    constexpr int NF  = WN / 8;
    constexpr int NCH = K / KC;
    constexpr int C8  = KC / 8;
    constexpr int AOFF = 0;
    constexpr int WOFF = BM * LDS;
    constexpr int SSZ  = (BM + NB) * LDS;

    extern __shared__ __half sm[];
    uint32_t u0 = smem_u32(sm);

    int tid  = threadIdx.x;
    int wid  = tid >> 5, lane = tid & 31;
    int wm0  = (wid / WARPS_N) * WM;
    int wn0  = (wid % WARPS_N) * WN;
    int m0   = blockIdx.x * BM;
    int n0   = blockIdx.y * NB;

    int a_r = lane & 15, a_c = (lane >> 4) * 8;
    int b_r = lane & 7,  b_c = ((lane >> 3) & 1) * 8;

    float acc[MF][NF][4];
    #pragma unroll
    for (int i = 0; i < MF; i++)
        #pragma unroll
        for (int j = 0; j < NF; j++)
            #pragma unroll
            for (int q = 0; q < 4; q++) acc[i][j][q] = 0.0f;

    auto issue = [&](int ch, int st) {
        int kc = ch * KC;
        uint32_t ub = u0 + (uint32_t)st * SSZ * 2;
        for (int i = tid; i < BM * C8; i += NT) {
            int r = i / C8, c = i % C8;
            cp16(ub + AOFF * 2 + (uint32_t)(r * LDS + c * 8) * 2,
                 A + (size_t)(m0 + r) * K + kc + c * 8);
        }
        for (int i = tid; i < NB * C8; i += NT) {
            int r = i / C8, c = i % C8;
            cp16(ub + WOFF * 2 + (uint32_t)(r * LDS + c * 8) * 2,
                 W + (size_t)(n0 + r) * K + kc + c * 8);
        }
        CP_COMMIT();
    };

    issue(0, 0);
    #pragma unroll
    for (int ch = 0; ch < NCH; ch++) {
        if (ch + 1 < NCH) {
            issue(ch + 1, (ch + 1) & 1);
            asm volatile("cp.async.wait_group 1;" ::: "memory");
        } else {
            asm volatile("cp.async.wait_group 0;" ::: "memory");
        }
        __syncthreads();

        uint32_t ub = u0 + (uint32_t)(ch & 1) * SSZ * 2;
        #pragma unroll
        for (int ks = 0; ks < KC / 16; ks++) {
            int k0 = ks * 16;
            uint32_t a[MF][4], b[NF][2];
            #pragma unroll
            for (int i = 0; i < MF; i++) {
                uint32_t off = (uint32_t)((wm0 + i * 16 + a_r) * LDS + k0 + a_c) * 2;
                ldsm4(ub + AOFF * 2 + off, a[i]);
            }
            #pragma unroll
            for (int j = 0; j < NF; j++) {
                uint32_t off = (uint32_t)((wn0 + j * 8 + b_r) * LDS + k0 + b_c) * 2;
                ldsm2(ub + WOFF * 2 + off, b[j]);
            }
            #pragma unroll
            for (int i = 0; i < MF; i++)
                #pragma unroll
                for (int j = 0; j < NF; j++)
                    mma16816h(acc[i][j], a[i], b[j]);
        }
        __syncthreads();
    }

    int gr = lane >> 2, t = lane & 3;
    #pragma unroll
    for (int i = 0; i < MF; i++) {
        #pragma unroll
        for (int j = 0; j < NF; j++) {
            int col = n0 + wn0 + j * 8 + 2 * t;
            #pragma unroll
            for (int h = 0; h < 2; h++) {
                int row = m0 + wm0 + i * 16 + gr + h * 8;
                float v0 = acc[i][j][h * 2 + 0];
                float v1 = acc[i][j][h * 2 + 1];
                if (BIAS) { v0 += bias[col]; v1 += bias[col + 1]; }
                if (RELU) { v0 = fmaxf(v0, 0.f); v1 = fmaxf(v1, 0.f); }
                if (DINV) { float d = g_dinv[row]; v0 *= d; v1 *= d; }
                *reinterpret_cast<__half2*>(C + (size_t)row * Ntotal + col) =
                    __floats2half2_rn(v0, v1);
            }
        }
    }
}

// ---------------- driver -----------------------------------------------------
extern "C" void kernel_launch(void* const* d_in, const int* in_sizes, int n_in,
                              void* d_out, int out_size) {
    const float* x  = (const float*)d_in[0];
    const int*   ei = (const int*)d_in[1];       // int32 (JAX x64 disabled)
    const float* W1 = (const float*)d_in[2];
    const float* b1 = (const float*)d_in[3];
    const float* W2 = (const float*)d_in[4];
    const float* b2 = (const float*)d_in[5];
    const float* W3 = (const float*)d_in[6];
    const float* b3 = (const float*)d_in[7];
    float*       out = (float*)d_out;

    const int n = in_sizes[0] / F_IN;   // 50000
    const int e = in_sizes[1] / 2;      // 800000

    __half *x16, *a1, *h1, *g2, *h2, *g3, *w1, *w2, *w3;
    cudaGetSymbolAddress((void**)&x16, g_x16);
    cudaGetSymbolAddress((void**)&a1,  g_a1);
    cudaGetSymbolAddress((void**)&h1,  g_h1);
    cudaGetSymbolAddress((void**)&g2,  g_g2);
    cudaGetSymbolAddress((void**)&h2,  g_h2);
    cudaGetSymbolAddress((void**)&g3,  g_g3);
    cudaGetSymbolAddress((void**)&w1,  g_w1);
    cudaGetSymbolAddress((void**)&w2,  g_w2);
    cudaGetSymbolAddress((void**)&w3,  g_w3);

    const int smem128 = 2 * (128 + 128) * 40 * 2;  // 40960
    const int smem32  = 2 * (128 + 32)  * 40 * 2;  // 25600
    cudaFuncSetAttribute(gemm_f16<128, 128, 4, 2, true,  true,  false>,
                         cudaFuncAttributeMaxDynamicSharedMemorySize, smem128);
    cudaFuncSetAttribute(gemm_f16<128, 256, 4, 2, false, false, true >,
                         cudaFuncAttributeMaxDynamicSharedMemorySize, smem128);
    cudaFuncSetAttribute(gemm_f16<32,  128, 8, 1, false, false, true >,
                         cudaFuncAttributeMaxDynamicSharedMemorySize, smem32);

    const int mt = M_PAD / 128;           // 391 row tiles
    const int nb = (n + 1023) / 1024;     // 49 scan blocks

    // launch 1: degree + weight transpose + scan-flag reset
    const int B_deg = (e + 255) / 256;
    const int B_w   = (65536 + 4096 + 255) / 256;
    prep_kernel<<<B_deg + B_w + 1, 256>>>(ei, W1, W2, W3, w1, w2, w3,
                                          e, B_deg, B_w);

    // launch 2: chained scan (dinv, rowptr, cursor, count reset)
    scan_chained_kernel<<<nb, 1024>>>(n, nb);

    // launch 3: x fp32 -> dinv-prescaled fp16 (single pass)
    conv_kernel<<<(n * 16 + 255) / 256, 256>>>(x, x16, n);

    // launch 4: CSR fill
    fill_csr_kernel<<<(e + 255) / 256, 256>>>(ei, e);

    // launch 5: agg1 (pure sum) -> a1
    agg16_kernel<F_IN, false, false, false><<<(n + 15) / 16, 128>>>(
        x16, nullptr, a1, nullptr, n);

    // launch 6: GEMM1 (128->256) + b1 + relu -> h1
    {
        dim3 grid(mt, 2);
        gemm_f16<128, 128, 4, 2, true, true, false><<<grid, 256, smem128>>>(
            a1, w1, b1, h1, n, F_H1);
    }

    // launch 7: GEMM2 (256->128) * dinv -> g2
    {
        dim3 grid(mt, 1);
        gemm_f16<128, 256, 4, 2, false, false, true><<<grid, 256, smem128>>>(
            h1, w2, nullptr, g2, n, F_H);
    }

    // launch 8: agg2 + b2 + relu -> h2
    agg16_kernel<F_H, true, true, false><<<(n + 15) / 16, 128>>>(
        g2, b2, h2, nullptr, n);

    // launch 9: GEMM3 (128->32) * dinv -> g3
    {
        dim3 grid(mt, 1);
        gemm_f16<32, 128, 8, 1, false, false, true><<<grid, 256, smem32>>>(
            h2, w3, nullptr, g3, n, F_OUT);
    }

    // launch 10: agg3 + b3 -> out fp32 (TPN=2, 64 nodes/block)
    agg16_kernel<F_OUT, true, false, true><<<(n + 63) / 64, 128>>>(
        g3, b3, nullptr, out, n);
}

// round 12
// speedup vs baseline: 1.0690x; 1.0690x over previous
#include <cuda_runtime.h>
#include <cuda_fp16.h>
#include <cstdint>

// Problem constants (fixed by dataset)
#define N_NODES 50000
#define N_EDGES 800000
#define F_IN   128
#define F_H1   256
#define F_H    128
#define F_OUT  32
#define M_PAD  50048   // 391 * 128

// ---------------- scratch (static device globals) ---------------------------
__device__ int   g_count [N_NODES];
__device__ float g_dinv  [M_PAD];        // pad rows stay 0
__device__ int   g_rowptr[N_NODES + 1];
__device__ int   g_cursor[N_NODES];
__device__ int   g_col   [N_EDGES];
__device__ int   g_pfx   [64];           // chained-scan prefix (+1; 0 = not ready)

// fp16 activations
__device__ __half g_x16[(size_t)N_NODES * F_IN];   // dinv-prescaled fp16 x
__device__ __half g_a1 [(size_t)M_PAD * F_IN];     // agg1 out (GEMM1 A)
__device__ __half g_h1 [(size_t)M_PAD * F_H1];
__device__ __half g_g2 [(size_t)M_PAD * F_H];
__device__ __half g_h2 [(size_t)M_PAD * F_H];
__device__ __half g_g3 [(size_t)M_PAD * F_OUT];
// transposed fp16 weights [N][K] (K-major rows)
__device__ __half g_w1[256 * 128];
__device__ __half g_w2[128 * 256];
__device__ __half g_w3[32 * 128];

// ---------------- PTX helpers ------------------------------------------------
__device__ __forceinline__ uint32_t smem_u32(const void* p) {
    uint32_t a;
    asm("{ .reg .u64 t; cvta.to.shared.u64 t, %1; cvt.u32.u64 %0, t; }"
        : "=r"(a) : "l"(p));
    return a;
}
__device__ __forceinline__ void ldsm4(uint32_t addr, uint32_t r[4]) {
    asm volatile("ldmatrix.sync.aligned.m8n8.x4.shared.b16 {%0,%1,%2,%3}, [%4];"
                 : "=r"(r[0]), "=r"(r[1]), "=r"(r[2]), "=r"(r[3]) : "r"(addr));
}
__device__ __forceinline__ void ldsm2(uint32_t addr, uint32_t r[2]) {
    asm volatile("ldmatrix.sync.aligned.m8n8.x2.shared.b16 {%0,%1}, [%2];"
                 : "=r"(r[0]), "=r"(r[1]) : "r"(addr));
}
__device__ __forceinline__ void mma16816h(float* c, const uint32_t* a, const uint32_t* b) {
    asm volatile(
        "mma.sync.aligned.m16n8k16.row.col.f32.f16.f16.f32 "
        "{%0,%1,%2,%3}, {%4,%5,%6,%7}, {%8,%9}, {%0,%1,%2,%3};"
        : "+f"(c[0]), "+f"(c[1]), "+f"(c[2]), "+f"(c[3])
        : "r"(a[0]), "r"(a[1]), "r"(a[2]), "r"(a[3]), "r"(b[0]), "r"(b[1]));
}
__device__ __forceinline__ void cp16(uint32_t saddr, const void* gaddr) {
    asm volatile("cp.async.cg.shared.global [%0], [%1], 16;"
                 :: "r"(saddr), "l"(gaddr));
}
#define CP_COMMIT() asm volatile("cp.async.commit_group;" ::: "memory")

// ---------------- launch 1: fused prep (degree(x4) + W transpose + flags) ----
__global__ __launch_bounds__(256)
void prep_kernel(const int* __restrict__ ei,
                 const float* __restrict__ W1, const float* __restrict__ W2,
                 const float* __restrict__ W3,
                 __half* w1, __half* w2, __half* w3,
                 int e, int B_deg, int B_w) {
    int bid = blockIdx.x, tid = threadIdx.x;
    if (bid < B_deg) {                                   // degree atomics, 4/thread
        int i0 = (bid * 256 + tid) * 4;
        if (i0 + 4 <= e) {
            int4 d = *reinterpret_cast<const int4*>(ei + e + i0);
            atomicAdd(&g_count[d.x], 1);
            atomicAdd(&g_count[d.y], 1);
            atomicAdd(&g_count[d.z], 1);
            atomicAdd(&g_count[d.w], 1);
        } else {
            for (int j = i0; j < e; j++) atomicAdd(&g_count[ei[e + j]], 1);
        }
    } else if (bid < B_deg + B_w) {                      // weight transpose (fp16)
        int idx = (bid - B_deg) * 256 + tid;
        if (idx < 32768) {                               // W1 [128,256] -> [256][128]
            int nn = idx / 128, k = idx % 128;
            w1[idx] = __float2half(W1[k * 256 + nn]);
        } else if (idx < 65536) {                        // W2 [256,128] -> [128][256]
            int i2 = idx - 32768;
            int nn = i2 / 256, k = i2 % 256;
            w2[i2] = __float2half(W2[k * 128 + nn]);
        } else if (idx < 65536 + 4096) {                 // W3 [128,32] -> [32][128]
            int i3 = idx - 65536;
            int nn = i3 / 128, k = i3 % 128;
            w3[i3] = __float2half(W3[k * 32 + nn]);
        }
    } else {                                             // zero scan flags
        if (tid < 64) g_pfx[tid] = 0;
    }
}

// ---------------- launch 2: chained single-pass scan -------------------------
__global__ __launch_bounds__(1024)
void scan_chained_kernel(int n, int nb) {
    __shared__ int temp[1024];
    __shared__ int pfx_sh;
    int bid = blockIdx.x, tid = threadIdx.x;
    int i = bid * 1024 + tid;
    int v = (i < n) ? g_count[i] : 0;
    if (i < n) {
        g_dinv[i]  = rsqrtf((float)(v + 1));   // +1 self-loop
        g_count[i] = 0;                        // reset for next replay
    }
    temp[tid] = v;
    __syncthreads();
    #pragma unroll
    for (int off = 1; off < 1024; off <<= 1) {
        int t = (tid >= off) ? temp[tid - off] : 0;
        __syncthreads();
        temp[tid] += t;
        __syncthreads();
    }
    if (tid == 0) {
        int p = 0;
        if (bid > 0) {
            while ((p = atomicAdd(&g_pfx[bid - 1], 0)) == 0) __nanosleep(20);
            p -= 1;
        }
        atomicExch(&g_pfx[bid], p + temp[1023] + 1);
        pfx_sh = p;
    }
    __syncthreads();
    int base = pfx_sh;
    if (i < n) {
        int excl = base + temp[tid] - v;
        g_rowptr[i] = excl;
        g_cursor[i] = excl;
    }
    if (bid == nb - 1 && tid == 1023) g_rowptr[n] = base + temp[1023];
}

// ---------------- launch 3: x fp32 -> dinv-prescaled fp16 (single pass) -----
__global__ __launch_bounds__(256)
void conv_kernel(const float* __restrict__ x, __half* __restrict__ x16, int n) {
    int i = blockIdx.x * blockDim.x + threadIdx.x;
    int node = i >> 4, lane = i & 15;
    if (node >= n) return;
    float di = g_dinv[node];
    const float4* xv = (const float4*)x;
    float4 a = xv[(size_t)node * 32 + lane * 2];
    float4 b = xv[(size_t)node * 32 + lane * 2 + 1];
    __half2 h0 = __floats2half2_rn(di * a.x, di * a.y);
    __half2 h1 = __floats2half2_rn(di * a.z, di * a.w);
    __half2 h2 = __floats2half2_rn(di * b.x, di * b.y);
    __half2 h3 = __floats2half2_rn(di * b.z, di * b.w);
    uint4 o;
    o.x = *reinterpret_cast<uint32_t*>(&h0);
    o.y = *reinterpret_cast<uint32_t*>(&h1);
    o.z = *reinterpret_cast<uint32_t*>(&h2);
    o.w = *reinterpret_cast<uint32_t*>(&h3);
    *reinterpret_cast<uint4*>(x16 + (size_t)node * F_IN + lane * 8) = o;
}

// ---------------- launch 4: CSR fill (4 edges/thread, MLP=4) -----------------
__global__ __launch_bounds__(256)
void fill_csr_kernel(const int* __restrict__ ei, int e) {
    int i0 = (blockIdx.x * blockDim.x + threadIdx.x) * 4;
    if (i0 + 4 <= e) {
        int4 s = *reinterpret_cast<const int4*>(ei + i0);
        int4 d = *reinterpret_cast<const int4*>(ei + e + i0);
        int p0 = atomicAdd(&g_cursor[d.x], 1);
        int p1 = atomicAdd(&g_cursor[d.y], 1);
        int p2 = atomicAdd(&g_cursor[d.z], 1);
        int p3 = atomicAdd(&g_cursor[d.w], 1);
        g_col[p0] = s.x;
        g_col[p1] = s.y;
        g_col[p2] = s.z;
        g_col[p3] = s.w;
    } else {
        for (int j = i0; j < e; j++) {
            int pos = atomicAdd(&g_cursor[ei[e + j]], 1);
            g_col[pos] = ei[j];
        }
    }
}

// ---------------- fp16 pull aggregation (16B/thread, unroll 8, hadd2 pairs) --
// (round-10 geometry: TPN = F/8 — the fastest measured variant)
__device__ __forceinline__ void add8(float* acc, uint4 v) {
    const __half2* h = reinterpret_cast<const __half2*>(&v);
    #pragma unroll
    for (int q = 0; q < 4; q++) {
        float2 f = __half22float2(h[q]);
        acc[2 * q] += f.x; acc[2 * q + 1] += f.y;
    }
}
__device__ __forceinline__ uint4 hadd2x4(uint4 a, uint4 b) {
    const __half2* pa = reinterpret_cast<const __half2*>(&a);
    const __half2* pb = reinterpret_cast<const __half2*>(&b);
    uint4 r;
    __half2* pr = reinterpret_cast<__half2*>(&r);
    #pragma unroll
    for (int q = 0; q < 4; q++) pr[q] = __hadd2(pa[q], pb[q]);
    return r;
}

// out[d] = dinv[d]*(g[d] + sum g[s]) (+bias)(relu); g rows dinv[src]-prescaled.
template <int F, bool BIAS, bool RELU, bool OUT32>
__global__ void agg16_kernel(const __half* __restrict__ g,
                             const float* __restrict__ bias,
                             __half* __restrict__ outh,
                             float* __restrict__ outf, int n) {
    constexpr int TPN = F / 8;
    constexpr uint32_t RB = F * 2;     // row bytes (total < 26MB fits 32-bit)
    int npb  = blockDim.x / TPN;
    int node = blockIdx.x * npb + threadIdx.x / TPN;
    if (node >= n) return;
    int lane = threadIdx.x % TPN;

    const char* base = (const char*)g + lane * 16;
    float acc[8];
    #pragma unroll
    for (int q = 0; q < 8; q++) acc[q] = 0.0f;
    add8(acc, *reinterpret_cast<const uint4*>(base + (uint32_t)node * RB));  // self

    int e  = g_rowptr[node];
    int e1 = g_rowptr[node + 1];
    for (; e + 8 <= e1; e += 8) {
        uint32_t off[8];
        uint4 v[8];
        #pragma unroll
        for (int j = 0; j < 8; j++) off[j] = (uint32_t)g_col[e + j] * RB;
        #pragma unroll
        for (int j = 0; j < 8; j++) v[j] = *reinterpret_cast<const uint4*>(base + off[j]);
        #pragma unroll
        for (int p = 0; p < 4; p++) {             // one-level fp16 pairwise
            uint4 w = hadd2x4(v[2 * p], v[2 * p + 1]);
            add8(acc, w);
        }
    }
    for (; e < e1; e++)
        add8(acc, *reinterpret_cast<const uint4*>(base + (uint32_t)g_col[e] * RB));

    float di = g_dinv[node];
    #pragma unroll
    for (int q = 0; q < 8; q++) acc[q] *= di;
    if (BIAS) {
        const float4* bp = (const float4*)(bias + lane * 8);
        float4 b0 = bp[0], b1 = bp[1];
        acc[0] += b0.x; acc[1] += b0.y; acc[2] += b0.z; acc[3] += b0.w;
        acc[4] += b1.x; acc[5] += b1.y; acc[6] += b1.z; acc[7] += b1.w;
    }
    if (RELU) {
        #pragma unroll
        for (int q = 0; q < 8; q++) acc[q] = fmaxf(acc[q], 0.0f);
    }
    if constexpr (OUT32) {
        size_t o = (size_t)node * F + lane * 8;
        *reinterpret_cast<float4*>(outf + o)     = make_float4(acc[0], acc[1], acc[2], acc[3]);
        *reinterpret_cast<float4*>(outf + o + 4) = make_float4(acc[4], acc[5], acc[6], acc[7]);
    } else {
        uint4 o16;
        __half2 p0 = __floats2half2_rn(acc[0], acc[1]);
        __half2 p1 = __floats2half2_rn(acc[2], acc[3]);
        __half2 p2 = __floats2half2_rn(acc[4], acc[5]);
        __half2 p3 = __floats2half2_rn(acc[6], acc[7]);
        o16.x = *reinterpret_cast<uint32_t*>(&p0);
        o16.y = *reinterpret_cast<uint32_t*>(&p1);
        o16.z = *reinterpret_cast<uint32_t*>(&p2);
        o16.w = *reinterpret_cast<uint32_t*>(&p3);
        *reinterpret_cast<uint4*>(outh + (size_t)node * F + lane * 8) = o16;
    }
}

// ---------------- fp16 GEMM (single W), cp.async 2-stage ---------------------
template <int NB, int K, int WARPS_M, int WARPS_N, bool BIAS, bool RELU, bool DINV>
__global__ __launch_bounds__(32 * WARPS_M * WARPS_N)
void gemm_f16(const __half* __restrict__ A, const __half* __restrict__ W,
              const float* __restrict__ bias,
              __half* __restrict__ C, int M, int Ntotal) {
    constexpr int BM  = 128;
    constexpr int KC  = 32;
    constexpr int LDS = KC + 8;
    constexpr int NT  = 32 * WARPS_M * WARPS_N;
    constexpr int WM  = BM / WARPS_M;
    constexpr int WN  = NB / WARPS_N;
    constexpr int MF  = WM / 16;
    constexpr int NF  = WN / 8;
    constexpr int NCH = K / KC;
    constexpr int C8  = KC / 8;
    constexpr int AOFF = 0;
    constexpr int WOFF = BM * LDS;
    constexpr int SSZ  = (BM + NB) * LDS;

    extern __shared__ __half sm[];
    uint32_t u0 = smem_u32(sm);

    int tid  = threadIdx.x;
    int wid  = tid >> 5, lane = tid & 31;
    int wm0  = (wid / WARPS_N) * WM;
    int wn0  = (wid % WARPS_N) * WN;
    int m0   = blockIdx.x * BM;
    int n0   = blockIdx.y * NB;

    int a_r = lane & 15, a_c = (lane >> 4) * 8;
    int b_r = lane & 7,  b_c = ((lane >> 3) & 1) * 8;

    float acc[MF][NF][4];
    #pragma unroll
    for (int i = 0; i < MF; i++)
        #pragma unroll
        for (int j = 0; j < NF; j++)
            #pragma unroll
            for (int q = 0; q < 4; q++) acc[i][j][q] = 0.0f;

    auto issue = [&](int ch, int st) {
        int kc = ch * KC;
        uint32_t ub = u0 + (uint32_t)st * SSZ * 2;
        for (int i = tid; i < BM * C8; i += NT) {
            int r = i / C8, c = i % C8;
            cp16(ub + AOFF * 2 + (uint32_t)(r * LDS + c * 8) * 2,
                 A + (size_t)(m0 + r) * K + kc + c * 8);
        }
        for (int i = tid; i < NB * C8; i += NT) {
            int r = i / C8, c = i % C8;
            cp16(ub + WOFF * 2 + (uint32_t)(r * LDS + c * 8) * 2,
                 W + (size_t)(n0 + r) * K + kc + c * 8);
        }
        CP_COMMIT();
    };

    issue(0, 0);
    #pragma unroll
    for (int ch = 0; ch < NCH; ch++) {
        if (ch + 1 < NCH) {
            issue(ch + 1, (ch + 1) & 1);
            asm volatile("cp.async.wait_group 1;" ::: "memory");
        } else {
            asm volatile("cp.async.wait_group 0;" ::: "memory");
        }
        __syncthreads();

        uint32_t ub = u0 + (uint32_t)(ch & 1) * SSZ * 2;
        #pragma unroll
        for (int ks = 0; ks < KC / 16; ks++) {
            int k0 = ks * 16;
            uint32_t a[MF][4], b[NF][2];
            #pragma unroll
            for (int i = 0; i < MF; i++) {
                uint32_t off = (uint32_t)((wm0 + i * 16 + a_r) * LDS + k0 + a_c) * 2;
                ldsm4(ub + AOFF * 2 + off, a[i]);
            }
            #pragma unroll
            for (int j = 0; j < NF; j++) {
                uint32_t off = (uint32_t)((wn0 + j * 8 + b_r) * LDS + k0 + b_c) * 2;
                ldsm2(ub + WOFF * 2 + off, b[j]);
            }
            #pragma unroll
            for (int i = 0; i < MF; i++)
                #pragma unroll
                for (int j = 0; j < NF; j++)
                    mma16816h(acc[i][j], a[i], b[j]);
        }
        __syncthreads();
    }

    int gr = lane >> 2, t = lane & 3;
    #pragma unroll
    for (int i = 0; i < MF; i++) {
        #pragma unroll
        for (int j = 0; j < NF; j++) {
            int col = n0 + wn0 + j * 8 + 2 * t;
            #pragma unroll
            for (int h = 0; h < 2; h++) {
                int row = m0 + wm0 + i * 16 + gr + h * 8;
                float v0 = acc[i][j][h * 2 + 0];
                float v1 = acc[i][j][h * 2 + 1];
                if (BIAS) { v0 += bias[col]; v1 += bias[col + 1]; }
                if (RELU) { v0 = fmaxf(v0, 0.f); v1 = fmaxf(v1, 0.f); }
                if (DINV) { float d = g_dinv[row]; v0 *= d; v1 *= d; }
                *reinterpret_cast<__half2*>(C + (size_t)row * Ntotal + col) =
                    __floats2half2_rn(v0, v1);
            }
        }
    }
}

// ---------------- driver -----------------------------------------------------
extern "C" void kernel_launch(void* const* d_in, const int* in_sizes, int n_in,
                              void* d_out, int out_size) {
    const float* x  = (const float*)d_in[0];
    const int*   ei = (const int*)d_in[1];       // int32 (JAX x64 disabled)
    const float* W1 = (const float*)d_in[2];
    const float* b1 = (const float*)d_in[3];
    const float* W2 = (const float*)d_in[4];
    const float* b2 = (const float*)d_in[5];
    const float* W3 = (const float*)d_in[6];
    const float* b3 = (const float*)d_in[7];
    float*       out = (float*)d_out;

    const int n = in_sizes[0] / F_IN;   // 50000
    const int e = in_sizes[1] / 2;      // 800000

    __half *x16, *a1, *h1, *g2, *h2, *g3, *w1, *w2, *w3;
    cudaGetSymbolAddress((void**)&x16, g_x16);
    cudaGetSymbolAddress((void**)&a1,  g_a1);
    cudaGetSymbolAddress((void**)&h1,  g_h1);
    cudaGetSymbolAddress((void**)&g2,  g_g2);
    cudaGetSymbolAddress((void**)&h2,  g_h2);
    cudaGetSymbolAddress((void**)&g3,  g_g3);
    cudaGetSymbolAddress((void**)&w1,  g_w1);
    cudaGetSymbolAddress((void**)&w2,  g_w2);
    cudaGetSymbolAddress((void**)&w3,  g_w3);

    const int smem128 = 2 * (128 + 128) * 40 * 2;  // 40960
    const int smem32  = 2 * (128 + 32)  * 40 * 2;  // 25600
    cudaFuncSetAttribute(gemm_f16<128, 128, 4, 2, true,  true,  false>,
                         cudaFuncAttributeMaxDynamicSharedMemorySize, smem128);
    cudaFuncSetAttribute(gemm_f16<128, 256, 4, 2, false, false, true >,
                         cudaFuncAttributeMaxDynamicSharedMemorySize, smem128);
    cudaFuncSetAttribute(gemm_f16<32,  128, 8, 1, false, false, true >,
                         cudaFuncAttributeMaxDynamicSharedMemorySize, smem32);

    const int mt = M_PAD / 128;           // 391 row tiles
    const int nb = (n + 1023) / 1024;     // 49 scan blocks

    // launch 1: degree(x4/thread) + weight transpose + scan-flag reset
    const int B_deg = (e / 4 + 255) / 256;            // 782
    const int B_w   = (65536 + 4096 + 255) / 256;
    prep_kernel<<<B_deg + B_w + 1, 256>>>(ei, W1, W2, W3, w1, w2, w3,
                                          e, B_deg, B_w);

    // launch 2: chained scan (dinv, rowptr, cursor, count reset)
    scan_chained_kernel<<<nb, 1024>>>(n, nb);

    // launch 3: x fp32 -> dinv-prescaled fp16 (single pass)
    conv_kernel<<<(n * 16 + 255) / 256, 256>>>(x, x16, n);

    // launch 4: CSR fill (4 edges/thread)
    fill_csr_kernel<<<(e / 4 + 255) / 256, 256>>>(ei, e);

    // launch 5: agg1 (pure sum) -> a1
    agg16_kernel<F_IN, false, false, false><<<(n + 7) / 8, 128>>>(
        x16, nullptr, a1, nullptr, n);

    // launch 6: GEMM1 (128->256) + b1 + relu -> h1
    {
        dim3 grid(mt, 2);
        gemm_f16<128, 128, 4, 2, true, true, false><<<grid, 256, smem128>>>(
            a1, w1, b1, h1, n, F_H1);
    }

    // launch 7: GEMM2 (256->128) * dinv -> g2
    {
        dim3 grid(mt, 1);
        gemm_f16<128, 256, 4, 2, false, false, true><<<grid, 256, smem128>>>(
            h1, w2, nullptr, g2, n, F_H);
    }

    // launch 8: agg2 + b2 + relu -> h2
    agg16_kernel<F_H, true, true, false><<<(n + 7) / 8, 128>>>(
        g2, b2, h2, nullptr, n);

    // launch 9: GEMM3 (128->32) * dinv -> g3
    {
        dim3 grid(mt, 1);
        gemm_f16<32, 128, 8, 1, false, false, true><<<grid, 256, smem32>>>(
            h2, w3, nullptr, g3, n, F_OUT);
    }

    // launch 10: agg3 + b3 -> out fp32
    agg16_kernel<F_OUT, true, false, true><<<(n + 31) / 32, 128>>>(
        g3, b3, nullptr, out, n);
}

// round 13
// speedup vs baseline: 1.1437x; 1.0699x over previous
#include <cuda_runtime.h>
#include <cuda_fp16.h>
#include <cstdint>

// Problem constants (fixed by dataset)
#define N_NODES 50000
#define N_EDGES 800000
#define F_IN   128
#define F_H1   256
#define F_H    128
#define F_OUT  32
#define M_PAD  50048   // 391 * 128

// ---------------- scratch (static device globals) ---------------------------
__device__ int   g_count [N_NODES];
__device__ float g_dinv  [M_PAD];        // pad rows stay 0
__device__ int   g_rowptr[N_NODES + 1];
__device__ int   g_cursor[N_NODES];
__device__ int   g_col   [N_EDGES];
__device__ int   g_pfx   [64];           // chained-scan prefix (+1; 0 = not ready)

// fp16 activations
__device__ __half g_x16[(size_t)N_NODES * F_IN];   // dinv-prescaled fp16 x
__device__ __half g_a1 [(size_t)M_PAD * F_IN];     // agg1 out (GEMM1 A)
__device__ __half g_h1 [(size_t)M_PAD * F_H1];
__device__ __half g_g2 [(size_t)M_PAD * F_H];
__device__ __half g_h2 [(size_t)M_PAD * F_H];
__device__ __half g_g3 [(size_t)M_PAD * F_OUT];
// transposed fp16 weights [N][K] (K-major rows)
__device__ __half g_w1[256 * 128];
__device__ __half g_w2[128 * 256];
__device__ __half g_w3[32 * 128];

// ---------------- PTX helpers ------------------------------------------------
__device__ __forceinline__ uint32_t smem_u32(const void* p) {
    uint32_t a;
    asm("{ .reg .u64 t; cvta.to.shared.u64 t, %1; cvt.u32.u64 %0, t; }"
        : "=r"(a) : "l"(p));
    return a;
}
__device__ __forceinline__ void ldsm4(uint32_t addr, uint32_t r[4]) {
    asm volatile("ldmatrix.sync.aligned.m8n8.x4.shared.b16 {%0,%1,%2,%3}, [%4];"
                 : "=r"(r[0]), "=r"(r[1]), "=r"(r[2]), "=r"(r[3]) : "r"(addr));
}
__device__ __forceinline__ void ldsm2(uint32_t addr, uint32_t r[2]) {
    asm volatile("ldmatrix.sync.aligned.m8n8.x2.shared.b16 {%0,%1}, [%2];"
                 : "=r"(r[0]), "=r"(r[1]) : "r"(addr));
}
__device__ __forceinline__ void mma16816h(float* c, const uint32_t* a, const uint32_t* b) {
    asm volatile(
        "mma.sync.aligned.m16n8k16.row.col.f32.f16.f16.f32 "
        "{%0,%1,%2,%3}, {%4,%5,%6,%7}, {%8,%9}, {%0,%1,%2,%3};"
        : "+f"(c[0]), "+f"(c[1]), "+f"(c[2]), "+f"(c[3])
        : "r"(a[0]), "r"(a[1]), "r"(a[2]), "r"(a[3]), "r"(b[0]), "r"(b[1]));
}
__device__ __forceinline__ void cp16(uint32_t saddr, const void* gaddr) {
    asm volatile("cp.async.cg.shared.global [%0], [%1], 16;"
                 :: "r"(saddr), "l"(gaddr));
}
#define CP_COMMIT() asm volatile("cp.async.commit_group;" ::: "memory")

// ---------------- launch 1: fused prep (degree(x4) + W transpose + flags) ----
__global__ __launch_bounds__(256)
void prep_kernel(const int* __restrict__ ei,
                 const float* __restrict__ W1, const float* __restrict__ W2,
                 const float* __restrict__ W3,
                 __half* w1, __half* w2, __half* w3,
                 int e, int B_deg, int B_w) {
    int bid = blockIdx.x, tid = threadIdx.x;
    if (bid < B_deg) {                                   // degree atomics, 4/thread
        int i0 = (bid * 256 + tid) * 4;
        if (i0 + 4 <= e) {
            int4 d = *reinterpret_cast<const int4*>(ei + e + i0);
            atomicAdd(&g_count[d.x], 1);
            atomicAdd(&g_count[d.y], 1);
            atomicAdd(&g_count[d.z], 1);
            atomicAdd(&g_count[d.w], 1);
        } else {
            for (int j = i0; j < e; j++) atomicAdd(&g_count[ei[e + j]], 1);
        }
    } else if (bid < B_deg + B_w) {                      // weight transpose (fp16)
        int idx = (bid - B_deg) * 256 + tid;
        if (idx < 32768) {                               // W1 [128,256] -> [256][128]
            int nn = idx / 128, k = idx % 128;
            w1[idx] = __float2half(W1[k * 256 + nn]);
        } else if (idx < 65536) {                        // W2 [256,128] -> [128][256]
            int i2 = idx - 32768;
            int nn = i2 / 256, k = i2 % 256;
            w2[i2] = __float2half(W2[k * 128 + nn]);
        } else if (idx < 65536 + 4096) {                 // W3 [128,32] -> [32][128]
            int i3 = idx - 65536;
            int nn = i3 / 128, k = i3 % 128;
            w3[i3] = __float2half(W3[k * 32 + nn]);
        }
    } else {                                             // zero scan flags
        if (tid < 64) g_pfx[tid] = 0;
    }
}

// ---------------- launch 2: chained single-pass scan -------------------------
__global__ __launch_bounds__(1024)
void scan_chained_kernel(int n, int nb) {
    __shared__ int temp[1024];
    __shared__ int pfx_sh;
    int bid = blockIdx.x, tid = threadIdx.x;
    int i = bid * 1024 + tid;
    int v = (i < n) ? g_count[i] : 0;
    if (i < n) {
        g_dinv[i]  = rsqrtf((float)(v + 1));   // +1 self-loop
        g_count[i] = 0;                        // reset for next replay
    }
    temp[tid] = v;
    __syncthreads();
    #pragma unroll
    for (int off = 1; off < 1024; off <<= 1) {
        int t = (tid >= off) ? temp[tid - off] : 0;
        __syncthreads();
        temp[tid] += t;
        __syncthreads();
    }
    if (tid == 0) {
        int p = 0;
        if (bid > 0) {
            while ((p = atomicAdd(&g_pfx[bid - 1], 0)) == 0) __nanosleep(20);
            p -= 1;
        }
        atomicExch(&g_pfx[bid], p + temp[1023] + 1);
        pfx_sh = p;
    }
    __syncthreads();
    int base = pfx_sh;
    if (i < n) {
        int excl = base + temp[tid] - v;
        g_rowptr[i] = excl;
        g_cursor[i] = excl;
    }
    if (bid == nb - 1 && tid == 1023) g_rowptr[n] = base + temp[1023];
}

// ---------------- launch 3: FUSED csr-fill + x-convert (section dispatch) ----
// fill blocks FIRST (atomic-throughput-bound, longest); conv blocks backfill SMs.
__global__ __launch_bounds__(256)
void convfill_kernel(const float* __restrict__ x, __half* __restrict__ x16,
                     const int* __restrict__ ei, int n, int e, int B_fill) {
    int bid = blockIdx.x, tid = threadIdx.x;
    if (bid < B_fill) {                                  // CSR fill, 1 edge/thread
        int i = bid * 256 + tid;
        if (i < e) {
            int src = ei[i];
            int dst = ei[e + i];
            int pos = atomicAdd(&g_cursor[dst], 1);
            g_col[pos] = src;
        }
    } else {                                             // x -> dinv-prescaled fp16
        int i = (bid - B_fill) * 256 + tid;
        int node = i >> 4, lane = i & 15;
        if (node >= n) return;
        float di = g_dinv[node];
        const float4* xv = (const float4*)x;
        float4 a = xv[(size_t)node * 32 + lane * 2];
        float4 b = xv[(size_t)node * 32 + lane * 2 + 1];
        __half2 h0 = __floats2half2_rn(di * a.x, di * a.y);
        __half2 h1 = __floats2half2_rn(di * a.z, di * a.w);
        __half2 h2 = __floats2half2_rn(di * b.x, di * b.y);
        __half2 h3 = __floats2half2_rn(di * b.z, di * b.w);
        uint4 o;
        o.x = *reinterpret_cast<uint32_t*>(&h0);
        o.y = *reinterpret_cast<uint32_t*>(&h1);
        o.z = *reinterpret_cast<uint32_t*>(&h2);
        o.w = *reinterpret_cast<uint32_t*>(&h3);
        *reinterpret_cast<uint4*>(x16 + (size_t)node * F_IN + lane * 8) = o;
    }
}

// ---------------- fp16 pull aggregation (16B/thread, depth-2 hadd2 tree) -----
__device__ __forceinline__ void add8(float* acc, uint4 v) {
    const __half2* h = reinterpret_cast<const __half2*>(&v);
    #pragma unroll
    for (int q = 0; q < 4; q++) {
        float2 f = __half22float2(h[q]);
        acc[2 * q] += f.x; acc[2 * q + 1] += f.y;
    }
}
__device__ __forceinline__ uint4 hadd2x4(uint4 a, uint4 b) {
    const __half2* pa = reinterpret_cast<const __half2*>(&a);
    const __half2* pb = reinterpret_cast<const __half2*>(&b);
    uint4 r;
    __half2* pr = reinterpret_cast<__half2*>(&r);
    #pragma unroll
    for (int q = 0; q < 4; q++) pr[q] = __hadd2(pa[q], pb[q]);
    return r;
}

// out[d] = dinv[d]*(g[d] + sum g[s]) (+bias)(relu); g rows dinv[src]-prescaled.
template <int F, bool BIAS, bool RELU, bool OUT32>
__global__ void agg16_kernel(const __half* __restrict__ g,
                             const float* __restrict__ bias,
                             __half* __restrict__ outh,
                             float* __restrict__ outf, int n) {
    constexpr int TPN = F / 8;
    constexpr uint32_t RB = F * 2;     // row bytes (total < 26MB fits 32-bit)
    int npb  = blockDim.x / TPN;
    int node = blockIdx.x * npb + threadIdx.x / TPN;
    if (node >= n) return;
    int lane = threadIdx.x % TPN;

    const char* base = (const char*)g + lane * 16;
    float acc[8];
    #pragma unroll
    for (int q = 0; q < 8; q++) acc[q] = 0.0f;
    add8(acc, *reinterpret_cast<const uint4*>(base + (uint32_t)node * RB));  // self

    int e  = g_rowptr[node];
    int e1 = g_rowptr[node + 1];
    for (; e + 8 <= e1; e += 8) {
        uint32_t off[8];
        uint4 v[8];
        #pragma unroll
        for (int j = 0; j < 8; j++) off[j] = (uint32_t)g_col[e + j] * RB;
        #pragma unroll
        for (int j = 0; j < 8; j++) v[j] = *reinterpret_cast<const uint4*>(base + off[j]);
        // depth-2 fp16 pairwise tree: 8 -> 4 -> 2, then fp32 accumulate
        uint4 w0 = hadd2x4(v[0], v[1]);
        uint4 w1 = hadd2x4(v[2], v[3]);
        uint4 w2 = hadd2x4(v[4], v[5]);
        uint4 w3 = hadd2x4(v[6], v[7]);
        uint4 u0 = hadd2x4(w0, w1);
        uint4 u1 = hadd2x4(w2, w3);
        add8(acc, u0);
        add8(acc, u1);
    }
    for (; e + 2 <= e1; e += 2) {
        uint4 v0 = *reinterpret_cast<const uint4*>(base + (uint32_t)g_col[e] * RB);
        uint4 v1 = *reinterpret_cast<const uint4*>(base + (uint32_t)g_col[e + 1] * RB);
        add8(acc, hadd2x4(v0, v1));
    }
    if (e < e1)
        add8(acc, *reinterpret_cast<const uint4*>(base + (uint32_t)g_col[e] * RB));

    float di = g_dinv[node];
    #pragma unroll
    for (int q = 0; q < 8; q++) acc[q] *= di;
    if (BIAS) {
        const float4* bp = (const float4*)(bias + lane * 8);
        float4 b0 = bp[0], b1 = bp[1];
        acc[0] += b0.x; acc[1] += b0.y; acc[2] += b0.z; acc[3] += b0.w;
        acc[4] += b1.x; acc[5] += b1.y; acc[6] += b1.z; acc[7] += b1.w;
    }
    if (RELU) {
        #pragma unroll
        for (int q = 0; q < 8; q++) acc[q] = fmaxf(acc[q], 0.0f);
    }
    if constexpr (OUT32) {
        size_t o = (size_t)node * F + lane * 8;
        *reinterpret_cast<float4*>(outf + o)     = make_float4(acc[0], acc[1], acc[2], acc[3]);
        *reinterpret_cast<float4*>(outf + o + 4) = make_float4(acc[4], acc[5], acc[6], acc[7]);
    } else {
        uint4 o16;
        __half2 p0 = __floats2half2_rn(acc[0], acc[1]);
        __half2 p1 = __floats2half2_rn(acc[2], acc[3]);
        __half2 p2 = __floats2half2_rn(acc[4], acc[5]);
        __half2 p3 = __floats2half2_rn(acc[6], acc[7]);
        o16.x = *reinterpret_cast<uint32_t*>(&p0);
        o16.y = *reinterpret_cast<uint32_t*>(&p1);
        o16.z = *reinterpret_cast<uint32_t*>(&p2);
        o16.w = *reinterpret_cast<uint32_t*>(&p3);
        *reinterpret_cast<uint4*>(outh + (size_t)node * F + lane * 8) = o16;
    }
}

// ---------------- fp16 GEMM (single W), cp.async 2-stage ---------------------
template <int NB, int K, int WARPS_M, int WARPS_N, bool BIAS, bool RELU, bool DINV>
__global__ __launch_bounds__(32 * WARPS_M * WARPS_N)
void gemm_f16(const __half* __restrict__ A, const __half* __restrict__ W,
              const float* __restrict__ bias,
              __half* __restrict__ C, int M, int Ntotal) {
    constexpr int BM  = 128;
    constexpr int KC  = 32;
    constexpr int LDS = KC + 8;
    constexpr int NT  = 32 * WARPS_M * WARPS_N;
    constexpr int WM  = BM / WARPS_M;
    constexpr int WN  = NB / WARPS_N;
    constexpr int MF  = WM / 16;
    constexpr int NF  = WN / 8;
    constexpr int NCH = K / KC;
    constexpr int C8  = KC / 8;
    constexpr int AOFF = 0;
    constexpr int WOFF = BM * LDS;
    constexpr int SSZ  = (BM + NB) * LDS;

    extern __shared__ __half sm[];
    uint32_t u0 = smem_u32(sm);

    int tid  = threadIdx.x;
    int wid  = tid >> 5, lane = tid & 31;
    int wm0  = (wid / WARPS_N) * WM;
    int wn0  = (wid % WARPS_N) * WN;
    int m0   = blockIdx.x * BM;
    int n0   = blockIdx.y * NB;

    int a_r = lane & 15, a_c = (lane >> 4) * 8;
    int b_r = lane & 7,  b_c = ((lane >> 3) & 1) * 8;

    float acc[MF][NF][4];
    #pragma unroll
    for (int i = 0; i < MF; i++)
        #pragma unroll
        for (int j = 0; j < NF; j++)
            #pragma unroll
            for (int q = 0; q < 4; q++) acc[i][j][q] = 0.0f;

    auto issue = [&](int ch, int st) {
        int kc = ch * KC;
        uint32_t ub = u0 + (uint32_t)st * SSZ * 2;
        for (int i = tid; i < BM * C8; i += NT) {
            int r = i / C8, c = i % C8;
            cp16(ub + AOFF * 2 + (uint32_t)(r * LDS + c * 8) * 2,
                 A + (size_t)(m0 + r) * K + kc + c * 8);
        }
        for (int i = tid; i < NB * C8; i += NT) {
            int r = i / C8, c = i % C8;
            cp16(ub + WOFF * 2 + (uint32_t)(r * LDS + c * 8) * 2,
                 W + (size_t)(n0 + r) * K + kc + c * 8);
        }
        CP_COMMIT();
    };

    issue(0, 0);
    #pragma unroll
    for (int ch = 0; ch < NCH; ch++) {
        if (ch + 1 < NCH) {
            issue(ch + 1, (ch + 1) & 1);
            asm volatile("cp.async.wait_group 1;" ::: "memory");
        } else {
            asm volatile("cp.async.wait_group 0;" ::: "memory");
        }
        __syncthreads();

        uint32_t ub = u0 + (uint32_t)(ch & 1) * SSZ * 2;
        #pragma unroll
        for (int ks = 0; ks < KC / 16; ks++) {
            int k0 = ks * 16;
            uint32_t a[MF][4], b[NF][2];
            #pragma unroll
            for (int i = 0; i < MF; i++) {
                uint32_t off = (uint32_t)((wm0 + i * 16 + a_r) * LDS + k0 + a_c) * 2;
                ldsm4(ub + AOFF * 2 + off, a[i]);
            }
            #pragma unroll
            for (int j = 0; j < NF; j++) {
                uint32_t off = (uint32_t)((wn0 + j * 8 + b_r) * LDS + k0 + b_c) * 2;
                ldsm2(ub + WOFF * 2 + off, b[j]);
            }
            #pragma unroll
            for (int i = 0; i < MF; i++)
                #pragma unroll
                for (int j = 0; j < NF; j++)
                    mma16816h(acc[i][j], a[i], b[j]);
        }
        __syncthreads();
    }

    int gr = lane >> 2, t = lane & 3;
    #pragma unroll
    for (int i = 0; i < MF; i++) {
        #pragma unroll
        for (int j = 0; j < NF; j++) {
            int col = n0 + wn0 + j * 8 + 2 * t;
            #pragma unroll
            for (int h = 0; h < 2; h++) {
                int row = m0 + wm0 + i * 16 + gr + h * 8;
                float v0 = acc[i][j][h * 2 + 0];
                float v1 = acc[i][j][h * 2 + 1];
                if (BIAS) { v0 += bias[col]; v1 += bias[col + 1]; }
                if (RELU) { v0 = fmaxf(v0, 0.f); v1 = fmaxf(v1, 0.f); }
                if (DINV) { float d = g_dinv[row]; v0 *= d; v1 *= d; }
                *reinterpret_cast<__half2*>(C + (size_t)row * Ntotal + col) =
                    __floats2half2_rn(v0, v1);
            }
        }
    }
}

// ---------------- driver -----------------------------------------------------
extern "C" void kernel_launch(void* const* d_in, const int* in_sizes, int n_in,
                              void* d_out, int out_size) {
    const float* x  = (const float*)d_in[0];
    const int*   ei = (const int*)d_in[1];       // int32 (JAX x64 disabled)
    const float* W1 = (const float*)d_in[2];
    const float* b1 = (const float*)d_in[3];
    const float* W2 = (const float*)d_in[4];
    const float* b2 = (const float*)d_in[5];
    const float* W3 = (const float*)d_in[6];
    const float* b3 = (const float*)d_in[7];
    float*       out = (float*)d_out;

    const int n = in_sizes[0] / F_IN;   // 50000
    const int e = in_sizes[1] / 2;      // 800000

    __half *x16, *a1, *h1, *g2, *h2, *g3, *w1, *w2, *w3;
    cudaGetSymbolAddress((void**)&x16, g_x16);
    cudaGetSymbolAddress((void**)&a1,  g_a1);
    cudaGetSymbolAddress((void**)&h1,  g_h1);
    cudaGetSymbolAddress((void**)&g2,  g_g2);
    cudaGetSymbolAddress((void**)&h2,  g_h2);
    cudaGetSymbolAddress((void**)&g3,  g_g3);
    cudaGetSymbolAddress((void**)&w1,  g_w1);
    cudaGetSymbolAddress((void**)&w2,  g_w2);
    cudaGetSymbolAddress((void**)&w3,  g_w3);

    const int smem128 = 2 * (128 + 128) * 40 * 2;  // 40960
    const int smem32  = 2 * (128 + 32)  * 40 * 2;  // 25600
    cudaFuncSetAttribute(gemm_f16<128, 128, 4, 2, true,  true,  false>,
                         cudaFuncAttributeMaxDynamicSharedMemorySize, smem128);
    cudaFuncSetAttribute(gemm_f16<128, 256, 4, 2, false, false, true >,
                         cudaFuncAttributeMaxDynamicSharedMemorySize, smem128);
    cudaFuncSetAttribute(gemm_f16<32,  128, 8, 1, false, false, true >,
                         cudaFuncAttributeMaxDynamicSharedMemorySize, smem32);

    const int mt = M_PAD / 128;           // 391 row tiles
    const int nb = (n + 1023) / 1024;     // 49 scan blocks

    // launch 1: degree(x4/thread) + weight transpose + scan-flag reset
    const int B_deg = (e / 4 + 255) / 256;            // 782
    const int B_w   = (65536 + 4096 + 255) / 256;
    prep_kernel<<<B_deg + B_w + 1, 256>>>(ei, W1, W2, W3, w1, w2, w3,
                                          e, B_deg, B_w);

    // launch 2: chained scan (dinv, rowptr, cursor, count reset)
    scan_chained_kernel<<<nb, 1024>>>(n, nb);

    // launch 3: FUSED csr-fill (1 edge/thread) + x->prescaled-fp16
    const int B_fill = (e + 255) / 256;               // 3125
    const int B_conv = (n * 16 + 255) / 256;          // 3125
    convfill_kernel<<<B_fill + B_conv, 256>>>(x, x16, ei, n, e, B_fill);

    // launch 4: agg1 (pure sum) -> a1
    agg16_kernel<F_IN, false, false, false><<<(n + 7) / 8, 128>>>(
        x16, nullptr, a1, nullptr, n);

    // launch 5: GEMM1 (128->256) + b1 + relu -> h1
    {
        dim3 grid(mt, 2);
        gemm_f16<128, 128, 4, 2, true, true, false><<<grid, 256, smem128>>>(
            a1, w1, b1, h1, n, F_H1);
    }

    // launch 6: GEMM2 (256->128) * dinv -> g2
    {
        dim3 grid(mt, 1);
        gemm_f16<128, 256, 4, 2, false, false, true><<<grid, 256, smem128>>>(
            h1, w2, nullptr, g2, n, F_H);
    }

    // launch 7: agg2 + b2 + relu -> h2
    agg16_kernel<F_H, true, true, false><<<(n + 7) / 8, 128>>>(
        g2, b2, h2, nullptr, n);

    // launch 8: GEMM3 (128->32) * dinv -> g3
    {
        dim3 grid(mt, 1);
        gemm_f16<32, 128, 8, 1, false, false, true><<<grid, 256, smem32>>>(
            h2, w3, nullptr, g3, n, F_OUT);
    }

    // launch 9: agg3 + b3 -> out fp32
    agg16_kernel<F_OUT, true, false, true><<<(n + 31) / 32, 128>>>(
        g3, b3, nullptr, out, n);
}

// round 14
// speedup vs baseline: 1.2107x; 1.0586x over previous
#include <cuda_runtime.h>
#include <cuda_fp16.h>
#include <cstdint>

// Problem constants (fixed by dataset)
#define N_NODES 50000
#define N_EDGES 800000
#define F_IN   128
#define F_H1   256
#define F_H    128
#define F_OUT  32
#define M_PAD  50048   // 391 * 128

// ---------------- scratch (static device globals) ---------------------------
__device__ int   g_count [N_NODES];
__device__ float g_dinv  [M_PAD];        // pad rows stay 0
__device__ int   g_rowptr[N_NODES + 1];
__device__ int   g_cursor[N_NODES];
__device__ int   g_col   [N_EDGES];      // stores src<<8 (byte offset, 256B rows)
__device__ int   g_pfx   [64];           // chained-scan prefix (+1; 0 = not ready)

// fp16 activations
__device__ __half g_x16[(size_t)N_NODES * F_IN];   // dinv-prescaled fp16 x
__device__ __half g_a1 [(size_t)M_PAD * F_IN];     // agg1 out; pad rows stay 0
__device__ __half g_g2 [(size_t)M_PAD * F_H];      // dinv*(relu(a1@W1+b1)@W2)
__device__ __half g_h2 [(size_t)M_PAD * F_H];
__device__ __half g_g3 [(size_t)M_PAD * F_OUT];
// transposed fp16 weights [N][K] (K-major rows)
__device__ __half g_w1[256 * 128];
__device__ __half g_w2[128 * 256];
__device__ __half g_w3[32 * 128];

// ---------------- PTX helpers ------------------------------------------------
__device__ __forceinline__ uint32_t smem_u32(const void* p) {
    uint32_t a;
    asm("{ .reg .u64 t; cvta.to.shared.u64 t, %1; cvt.u32.u64 %0, t; }"
        : "=r"(a) : "l"(p));
    return a;
}
__device__ __forceinline__ void ldsm4(uint32_t addr, uint32_t r[4]) {
    asm volatile("ldmatrix.sync.aligned.m8n8.x4.shared.b16 {%0,%1,%2,%3}, [%4];"
                 : "=r"(r[0]), "=r"(r[1]), "=r"(r[2]), "=r"(r[3]) : "r"(addr));
}
__device__ __forceinline__ void ldsm2(uint32_t addr, uint32_t r[2]) {
    asm volatile("ldmatrix.sync.aligned.m8n8.x2.shared.b16 {%0,%1}, [%2];"
                 : "=r"(r[0]), "=r"(r[1]) : "r"(addr));
}
__device__ __forceinline__ void mma16816h(float* c, const uint32_t* a, const uint32_t* b) {
    asm volatile(
        "mma.sync.aligned.m16n8k16.row.col.f32.f16.f16.f32 "
        "{%0,%1,%2,%3}, {%4,%5,%6,%7}, {%8,%9}, {%0,%1,%2,%3};"
        : "+f"(c[0]), "+f"(c[1]), "+f"(c[2]), "+f"(c[3])
        : "r"(a[0]), "r"(a[1]), "r"(a[2]), "r"(a[3]), "r"(b[0]), "r"(b[1]));
}
__device__ __forceinline__ void cp16(uint32_t saddr, const void* gaddr) {
    asm volatile("cp.async.cg.shared.global [%0], [%1], 16;"
                 :: "r"(saddr), "l"(gaddr));
}
#define CP_COMMIT() asm volatile("cp.async.commit_group;" ::: "memory")

// ---------------- launch 1: fused prep (degree(x4) + W transpose + flags) ----
__global__ __launch_bounds__(256)
void prep_kernel(const int* __restrict__ ei,
                 const float* __restrict__ W1, const float* __restrict__ W2,
                 const float* __restrict__ W3,
                 __half* w1, __half* w2, __half* w3,
                 int e, int B_deg, int B_w) {
    int bid = blockIdx.x, tid = threadIdx.x;
    if (bid < B_deg) {                                   // degree atomics, 4/thread
        int i0 = (bid * 256 + tid) * 4;
        if (i0 + 4 <= e) {
            int4 d = *reinterpret_cast<const int4*>(ei + e + i0);
            atomicAdd(&g_count[d.x], 1);
            atomicAdd(&g_count[d.y], 1);
            atomicAdd(&g_count[d.z], 1);
            atomicAdd(&g_count[d.w], 1);
        } else {
            for (int j = i0; j < e; j++) atomicAdd(&g_count[ei[e + j]], 1);
        }
    } else if (bid < B_deg + B_w) {                      // weight transpose (fp16)
        int idx = (bid - B_deg) * 256 + tid;
        if (idx < 32768) {                               // W1 [128,256] -> [256][128]
            int nn = idx / 128, k = idx % 128;
            w1[idx] = __float2half(W1[k * 256 + nn]);
        } else if (idx < 65536) {                        // W2 [256,128] -> [128][256]
            int i2 = idx - 32768;
            int nn = i2 / 256, k = i2 % 256;
            w2[i2] = __float2half(W2[k * 128 + nn]);
        } else if (idx < 65536 + 4096) {                 // W3 [128,32] -> [32][128]
            int i3 = idx - 65536;
            int nn = i3 / 128, k = i3 % 128;
            w3[i3] = __float2half(W3[k * 32 + nn]);
        }
    } else {                                             // zero scan flags
        if (tid < 64) g_pfx[tid] = 0;
    }
}

// ---------------- launch 2: chained single-pass scan -------------------------
__global__ __launch_bounds__(1024)
void scan_chained_kernel(int n, int nb) {
    __shared__ int temp[1024];
    __shared__ int pfx_sh;
    int bid = blockIdx.x, tid = threadIdx.x;
    int i = bid * 1024 + tid;
    int v = (i < n) ? g_count[i] : 0;
    if (i < n) {
        g_dinv[i]  = rsqrtf((float)(v + 1));   // +1 self-loop
        g_count[i] = 0;                        // reset for next replay
    }
    temp[tid] = v;
    __syncthreads();
    #pragma unroll
    for (int off = 1; off < 1024; off <<= 1) {
        int t = (tid >= off) ? temp[tid - off] : 0;
        __syncthreads();
        temp[tid] += t;
        __syncthreads();
    }
    if (tid == 0) {
        int p = 0;
        if (bid > 0) {
            while ((p = atomicAdd(&g_pfx[bid - 1], 0)) == 0) __nanosleep(20);
            p -= 1;
        }
        atomicExch(&g_pfx[bid], p + temp[1023] + 1);
        pfx_sh = p;
    }
    __syncthreads();
    int base = pfx_sh;
    if (i < n) {
        int excl = base + temp[tid] - v;
        g_rowptr[i] = excl;
        g_cursor[i] = excl;
    }
    if (bid == nb - 1 && tid == 1023) g_rowptr[n] = base + temp[1023];
}

// ---------------- launch 3: FUSED csr-fill + x-convert (section dispatch) ----
__global__ __launch_bounds__(256)
void convfill_kernel(const float* __restrict__ x, __half* __restrict__ x16,
                     const int* __restrict__ ei, int n, int e, int B_fill) {
    int bid = blockIdx.x, tid = threadIdx.x;
    if (bid < B_fill) {                                  // CSR fill, 1 edge/thread
        int i = bid * 256 + tid;
        if (i < e) {
            int src = ei[i];
            int dst = ei[e + i];
            int pos = atomicAdd(&g_cursor[dst], 1);
            g_col[pos] = src << 8;                       // pre-shifted byte offset
        }
    } else {                                             // x -> dinv-prescaled fp16
        int i = (bid - B_fill) * 256 + tid;
        int node = i >> 4, lane = i & 15;
        if (node >= n) return;
        float di = g_dinv[node];
        const float4* xv = (const float4*)x;
        float4 a = xv[(size_t)node * 32 + lane * 2];
        float4 b = xv[(size_t)node * 32 + lane * 2 + 1];
        __half2 h0 = __floats2half2_rn(di * a.x, di * a.y);
        __half2 h1 = __floats2half2_rn(di * a.z, di * a.w);
        __half2 h2 = __floats2half2_rn(di * b.x, di * b.y);
        __half2 h3 = __floats2half2_rn(di * b.z, di * b.w);
        uint4 o;
        o.x = *reinterpret_cast<uint32_t*>(&h0);
        o.y = *reinterpret_cast<uint32_t*>(&h1);
        o.z = *reinterpret_cast<uint32_t*>(&h2);
        o.w = *reinterpret_cast<uint32_t*>(&h3);
        *reinterpret_cast<uint4*>(x16 + (size_t)node * F_IN + lane * 8) = o;
    }
}

// ---------------- fp16 pull aggregation (pre-shifted offsets, depth-3 tree) --
__device__ __forceinline__ void add8(float* acc, uint4 v) {
    const __half2* h = reinterpret_cast<const __half2*>(&v);
    #pragma unroll
    for (int q = 0; q < 4; q++) {
        float2 f = __half22float2(h[q]);
        acc[2 * q] += f.x; acc[2 * q + 1] += f.y;
    }
}
__device__ __forceinline__ uint4 hadd2x4(uint4 a, uint4 b) {
    const __half2* pa = reinterpret_cast<const __half2*>(&a);
    const __half2* pb = reinterpret_cast<const __half2*>(&b);
    uint4 r;
    __half2* pr = reinterpret_cast<__half2*>(&r);
    #pragma unroll
    for (int q = 0; q < 4; q++) pr[q] = __hadd2(pa[q], pb[q]);
    return r;
}

// out[d] = dinv[d]*(g[d] + sum g[s]) (+bias)(relu); g rows dinv[src]-prescaled.
// g_col holds src<<8 (byte offset for 256B rows); SH shifts down for smaller F.
template <int F, int SH, bool BIAS, bool RELU, bool OUT32>
__global__ void agg16_kernel(const __half* __restrict__ g,
                             const float* __restrict__ bias,
                             __half* __restrict__ outh,
                             float* __restrict__ outf, int n) {
    constexpr int TPN = F / 8;
    constexpr uint32_t RB = F * 2;     // row bytes
    int npb  = blockDim.x / TPN;
    int node = blockIdx.x * npb + threadIdx.x / TPN;
    if (node >= n) return;
    int lane = threadIdx.x % TPN;

    const char* base = (const char*)g + lane * 16;
    float acc[8];
    #pragma unroll
    for (int q = 0; q < 8; q++) acc[q] = 0.0f;
    add8(acc, *reinterpret_cast<const uint4*>(base + (uint32_t)node * RB));  // self

    int e  = g_rowptr[node];
    int e1 = g_rowptr[node + 1];
    for (; e + 8 <= e1; e += 8) {
        uint32_t off[8];
        uint4 v[8];
        #pragma unroll
        for (int j = 0; j < 8; j++) off[j] = (uint32_t)g_col[e + j] >> SH;
        #pragma unroll
        for (int j = 0; j < 8; j++) v[j] = *reinterpret_cast<const uint4*>(base + off[j]);
        // depth-3 fp16 tree: 8 -> 4 -> 2 -> 1, then one fp32 accumulate
        uint4 w0 = hadd2x4(v[0], v[1]);
        uint4 w1 = hadd2x4(v[2], v[3]);
        uint4 w2 = hadd2x4(v[4], v[5]);
        uint4 w3 = hadd2x4(v[6], v[7]);
        uint4 u0 = hadd2x4(w0, w1);
        uint4 u1 = hadd2x4(w2, w3);
        add8(acc, hadd2x4(u0, u1));
    }
    for (; e + 2 <= e1; e += 2) {
        uint4 v0 = *reinterpret_cast<const uint4*>(base + ((uint32_t)g_col[e] >> SH));
        uint4 v1 = *reinterpret_cast<const uint4*>(base + ((uint32_t)g_col[e + 1] >> SH));
        add8(acc, hadd2x4(v0, v1));
    }
    if (e < e1)
        add8(acc, *reinterpret_cast<const uint4*>(base + ((uint32_t)g_col[e] >> SH)));

    float di = g_dinv[node];
    #pragma unroll
    for (int q = 0; q < 8; q++) acc[q] *= di;
    if (BIAS) {
        const float4* bp = (const float4*)(bias + lane * 8);
        float4 b0 = bp[0], b1 = bp[1];
        acc[0] += b0.x; acc[1] += b0.y; acc[2] += b0.z; acc[3] += b0.w;
        acc[4] += b1.x; acc[5] += b1.y; acc[6] += b1.z; acc[7] += b1.w;
    }
    if (RELU) {
        #pragma unroll
        for (int q = 0; q < 8; q++) acc[q] = fmaxf(acc[q], 0.0f);
    }
    if constexpr (OUT32) {
        size_t o = (size_t)node * F + lane * 8;
        *reinterpret_cast<float4*>(outf + o)     = make_float4(acc[0], acc[1], acc[2], acc[3]);
        *reinterpret_cast<float4*>(outf + o + 4) = make_float4(acc[4], acc[5], acc[6], acc[7]);
    } else {
        uint4 o16;
        __half2 p0 = __floats2half2_rn(acc[0], acc[1]);
        __half2 p1 = __floats2half2_rn(acc[2], acc[3]);
        __half2 p2 = __floats2half2_rn(acc[4], acc[5]);
        __half2 p3 = __floats2half2_rn(acc[6], acc[7]);
        o16.x = *reinterpret_cast<uint32_t*>(&p0);
        o16.y = *reinterpret_cast<uint32_t*>(&p1);
        o16.z = *reinterpret_cast<uint32_t*>(&p2);
        o16.w = *reinterpret_cast<uint32_t*>(&p3);
        *reinterpret_cast<uint4*>(outh + (size_t)node * F + lane * 8) = o16;
    }
}

// ---------------- FUSED GEMM1+GEMM2 ------------------------------------------
// Per block (128 rows): h1 = relu(a1@W1^T + b1) kept in SMEM fp16,
// then g2 = dinv * (h1 @ W2^T). W1t [256][128], W2t [128][256] K-major.
#define LDS1 40     // KC(32)+8
#define LDS2 264    // 256+8
#define G12_SMEM ((2 * (128 + 256) * LDS1 + 2 * 128 * LDS2) * 2)   // 196608 B

__global__ __launch_bounds__(256)
void gemm12_kernel(const __half* __restrict__ A, const __half* __restrict__ W1t,
                   const __half* __restrict__ W2t, const float* __restrict__ b1,
                   __half* __restrict__ g2) {
    constexpr int KC = 32;
    constexpr int SSZ = (128 + 256) * LDS1;
    extern __shared__ __half sm[];
    __half* h1t = sm + 2 * SSZ;
    uint32_t u_stg = smem_u32(sm);
    uint32_t u_h1  = smem_u32(h1t);
    uint32_t u_w2  = u_h1 + 128 * LDS2 * 2;

    int tid = threadIdx.x, wid = tid >> 5, lane = tid & 31;
    int wm0 = (wid >> 2) * 64;      // 2 warps in M (WM=64)
    int wn0 = (wid & 3) * 64;       // 4 warps in N (phase1 WN=64)
    int m0  = blockIdx.x * 128;

    int a_r = lane & 15, a_c = (lane >> 4) * 8;
    int b_r = lane & 7,  b_c = ((lane >> 3) & 1) * 8;

    // W2 preload (joins commit group 0 below): 128 rows x 32 cp16
    for (int i = tid; i < 128 * 32; i += 256) {
        int r = i >> 5, c = i & 31;
        cp16(u_w2 + (uint32_t)(r * LDS2 + c * 8) * 2, W2t + (size_t)r * 256 + c * 8);
    }

    auto issue = [&](int ch, int st) {
        int kc = ch * KC;
        uint32_t ub = u_stg + (uint32_t)st * SSZ * 2;
        for (int i = tid; i < 128 * 4; i += 256) {
            int r = i >> 2, c = i & 3;
            cp16(ub + (uint32_t)(r * LDS1 + c * 8) * 2,
                 A + (size_t)(m0 + r) * 128 + kc + c * 8);
        }
        for (int i = tid; i < 256 * 4; i += 256) {
            int r = i >> 2, c = i & 3;
            cp16(ub + (uint32_t)((128 + r) * LDS1 + c * 8) * 2,
                 W1t + (size_t)r * 128 + kc + c * 8);
        }
        CP_COMMIT();
    };

    // ---- phase 1: C1[128,256] ----
    float acc[4][8][4];
    #pragma unroll
    for (int i = 0; i < 4; i++)
        #pragma unroll
        for (int j = 0; j < 8; j++)
            #pragma unroll
            for (int q = 0; q < 4; q++) acc[i][j][q] = 0.0f;

    issue(0, 0);        // group 0 also contains the W2 preload
    #pragma unroll
    for (int ch = 0; ch < 4; ch++) {
        if (ch + 1 < 4) {
            issue(ch + 1, (ch + 1) & 1);
            asm volatile("cp.async.wait_group 1;" ::: "memory");
        } else {
            asm volatile("cp.async.wait_group 0;" ::: "memory");
        }
        __syncthreads();
        uint32_t ub = u_stg + (uint32_t)(ch & 1) * SSZ * 2;
        #pragma unroll
        for (int ks = 0; ks < 2; ks++) {
            int k0 = ks * 16;
            uint32_t a[4][4], b[8][2];
            #pragma unroll
            for (int i = 0; i < 4; i++)
                ldsm4(ub + (uint32_t)((wm0 + i * 16 + a_r) * LDS1 + k0 + a_c) * 2, a[i]);
            #pragma unroll
            for (int j = 0; j < 8; j++)
                ldsm2(ub + (uint32_t)((128 + wn0 + j * 8 + b_r) * LDS1 + k0 + b_c) * 2, b[j]);
            #pragma unroll
            for (int i = 0; i < 4; i++)
                #pragma unroll
                for (int j = 0; j < 8; j++)
                    mma16816h(acc[i][j], a[i], b[j]);
        }
        __syncthreads();
    }

    // epilogue 1: bias + relu -> fp16 h1 tile in SMEM
    int gr = lane >> 2, t = lane & 3;
    #pragma unroll
    for (int i = 0; i < 4; i++) {
        #pragma unroll
        for (int j = 0; j < 8; j++) {
            int col = wn0 + j * 8 + 2 * t;
            #pragma unroll
            for (int h = 0; h < 2; h++) {
                int rl = wm0 + i * 16 + gr + h * 8;
                float v0 = acc[i][j][h * 2 + 0] + b1[col];
                float v1 = acc[i][j][h * 2 + 1] + b1[col + 1];
                v0 = fmaxf(v0, 0.f); v1 = fmaxf(v1, 0.f);
                *reinterpret_cast<__half2*>(&h1t[rl * LDS2 + col]) =
                    __floats2half2_rn(v0, v1);
            }
        }
    }
    __syncthreads();

    // ---- phase 2: g2[128,128] = dinv * (h1 @ W2^T), K=256 ----
    float acc2[4][4][4];
    #pragma unroll
    for (int i = 0; i < 4; i++)
        #pragma unroll
        for (int j = 0; j < 4; j++)
            #pragma unroll
            for (int q = 0; q < 4; q++) acc2[i][j][q] = 0.0f;
    int wn2 = (wid & 3) * 32;       // phase2 WN=32
    #pragma unroll
    for (int ks = 0; ks < 16; ks++) {
        int k0 = ks * 16;
        uint32_t a[4][4], b[4][2];
        #pragma unroll
        for (int i = 0; i < 4; i++)
            ldsm4(u_h1 + (uint32_t)((wm0 + i * 16 + a_r) * LDS2 + k0 + a_c) * 2, a[i]);
        #pragma unroll
        for (int j = 0; j < 4; j++)
            ldsm2(u_w2 + (uint32_t)((wn2 + j * 8 + b_r) * LDS2 + k0 + b_c) * 2, b[j]);
        #pragma unroll
        for (int i = 0; i < 4; i++)
            #pragma unroll
            for (int j = 0; j < 4; j++)
                mma16816h(acc2[i][j], a[i], b[j]);
    }

    // epilogue 2: * dinv[row] -> g2 fp16
    #pragma unroll
    for (int i = 0; i < 4; i++) {
        #pragma unroll
        for (int j = 0; j < 4; j++) {
            int col = wn2 + j * 8 + 2 * t;
            #pragma unroll
            for (int h = 0; h < 2; h++) {
                int row = m0 + wm0 + i * 16 + gr + h * 8;
                float d = g_dinv[row];
                float v0 = acc2[i][j][h * 2 + 0] * d;
                float v1 = acc2[i][j][h * 2 + 1] * d;
                *reinterpret_cast<__half2*>(g2 + (size_t)row * F_H + col) =
                    __floats2half2_rn(v0, v1);
            }
        }
    }
}

// ---------------- generic fp16 GEMM (for layer 3), cp.async 2-stage ----------
template <int NB, int K, int WARPS_M, int WARPS_N, bool BIAS, bool RELU, bool DINV>
__global__ __launch_bounds__(32 * WARPS_M * WARPS_N)
void gemm_f16(const __half* __restrict__ A, const __half* __restrict__ W,
              const float* __restrict__ bias,
              __half* __restrict__ C, int M, int Ntotal) {
    constexpr int BM  = 128;
    constexpr int KC  = 32;
    constexpr int LDS = KC + 8;
    constexpr int NT  = 32 * WARPS_M * WARPS_N;
    constexpr int WM  = BM / WARPS_M;
    constexpr int WN  = NB / WARPS_N;
    constexpr int MF  = WM / 16;
    constexpr int NF  = WN / 8;
    constexpr int NCH = K / KC;
    constexpr int C8  = KC / 8;
    constexpr int AOFF = 0;
    constexpr int WOFF = BM * LDS;
    constexpr int SSZ  = (BM + NB) * LDS;

    extern __shared__ __half sm[];
    uint32_t u0 = smem_u32(sm);

    int tid  = threadIdx.x;
    int wid  = tid >> 5, lane = tid & 31;
    int wm0  = (wid / WARPS_N) * WM;
    int wn0  = (wid % WARPS_N) * WN;
    int m0   = blockIdx.x * BM;
    int n0   = blockIdx.y * NB;

    int a_r = lane & 15, a_c = (lane >> 4) * 8;
    int b_r = lane & 7,  b_c = ((lane >> 3) & 1) * 8;

    float acc[MF][NF][4];
    #pragma unroll
    for (int i = 0; i < MF; i++)
        #pragma unroll
        for (int j = 0; j < NF; j++)
            #pragma unroll
            for (int q = 0; q < 4; q++) acc[i][j][q] = 0.0f;

    auto issue = [&](int ch, int st) {
        int kc = ch * KC;
        uint32_t ub = u0 + (uint32_t)st * SSZ * 2;
        for (int i = tid; i < BM * C8; i += NT) {
            int r = i / C8, c = i % C8;
            cp16(ub + AOFF * 2 + (uint32_t)(r * LDS + c * 8) * 2,
                 A + (size_t)(m0 + r) * K + kc + c * 8);
        }
        for (int i = tid; i < NB * C8; i += NT) {
            int r = i / C8, c = i % C8;
            cp16(ub + WOFF * 2 + (uint32_t)(r * LDS + c * 8) * 2,
                 W + (size_t)(n0 + r) * K + kc + c * 8);
        }
        CP_COMMIT();
    };

    issue(0, 0);
    #pragma unroll
    for (int ch = 0; ch < NCH; ch++) {
        if (ch + 1 < NCH) {
            issue(ch + 1, (ch + 1) & 1);
            asm volatile("cp.async.wait_group 1;" ::: "memory");
        } else {
            asm volatile("cp.async.wait_group 0;" ::: "memory");
        }
        __syncthreads();

        uint32_t ub = u0 + (uint32_t)(ch & 1) * SSZ * 2;
        #pragma unroll
        for (int ks = 0; ks < KC / 16; ks++) {
            int k0 = ks * 16;
            uint32_t a[MF][4], b[NF][2];
            #pragma unroll
            for (int i = 0; i < MF; i++) {
                uint32_t off = (uint32_t)((wm0 + i * 16 + a_r) * LDS + k0 + a_c) * 2;
                ldsm4(ub + AOFF * 2 + off, a[i]);
            }
            #pragma unroll
            for (int j = 0; j < NF; j++) {
                uint32_t off = (uint32_t)((wn0 + j * 8 + b_r) * LDS + k0 + b_c) * 2;
                ldsm2(ub + WOFF * 2 + off, b[j]);
            }
            #pragma unroll
            for (int i = 0; i < MF; i++)
                #pragma unroll
                for (int j = 0; j < NF; j++)
                    mma16816h(acc[i][j], a[i], b[j]);
        }
        __syncthreads();
    }

    int gr = lane >> 2, t = lane & 3;
    #pragma unroll
    for (int i = 0; i < MF; i++) {
        #pragma unroll
        for (int j = 0; j < NF; j++) {
            int col = n0 + wn0 + j * 8 + 2 * t;
            #pragma unroll
            for (int h = 0; h < 2; h++) {
                int row = m0 + wm0 + i * 16 + gr + h * 8;
                float v0 = acc[i][j][h * 2 + 0];
                float v1 = acc[i][j][h * 2 + 1];
                if (BIAS) { v0 += bias[col]; v1 += bias[col + 1]; }
                if (RELU) { v0 = fmaxf(v0, 0.f); v1 = fmaxf(v1, 0.f); }
                if (DINV) { float d = g_dinv[row]; v0 *= d; v1 *= d; }
                *reinterpret_cast<__half2*>(C + (size_t)row * Ntotal + col) =
                    __floats2half2_rn(v0, v1);
            }
        }
    }
}

// ---------------- driver -----------------------------------------------------
extern "C" void kernel_launch(void* const* d_in, const int* in_sizes, int n_in,
                              void* d_out, int out_size) {
    const float* x  = (const float*)d_in[0];
    const int*   ei = (const int*)d_in[1];       // int32 (JAX x64 disabled)
    const float* W1 = (const float*)d_in[2];
    const float* b1 = (const float*)d_in[3];
    const float* W2 = (const float*)d_in[4];
    const float* b2 = (const float*)d_in[5];
    const float* W3 = (const float*)d_in[6];
    const float* b3 = (const float*)d_in[7];
    float*       out = (float*)d_out;

    const int n = in_sizes[0] / F_IN;   // 50000
    const int e = in_sizes[1] / 2;      // 800000

    __half *x16, *a1, *g2, *h2, *g3, *w1, *w2, *w3;
    cudaGetSymbolAddress((void**)&x16, g_x16);
    cudaGetSymbolAddress((void**)&a1,  g_a1);
    cudaGetSymbolAddress((void**)&g2,  g_g2);
    cudaGetSymbolAddress((void**)&h2,  g_h2);
    cudaGetSymbolAddress((void**)&g3,  g_g3);
    cudaGetSymbolAddress((void**)&w1,  g_w1);
    cudaGetSymbolAddress((void**)&w2,  g_w2);
    cudaGetSymbolAddress((void**)&w3,  g_w3);

    const int smem32 = 2 * (128 + 32) * 40 * 2;   // 25600
    cudaFuncSetAttribute(gemm12_kernel,
                         cudaFuncAttributeMaxDynamicSharedMemorySize, G12_SMEM);
    cudaFuncSetAttribute(gemm_f16<32, 128, 8, 1, false, false, true>,
                         cudaFuncAttributeMaxDynamicSharedMemorySize, smem32);

    const int mt = M_PAD / 128;           // 391 row tiles
    const int nb = (n + 1023) / 1024;     // 49 scan blocks

    // launch 1: degree(x4/thread) + weight transpose + scan-flag reset
    const int B_deg = (e / 4 + 255) / 256;
    const int B_w   = (65536 + 4096 + 255) / 256;
    prep_kernel<<<B_deg + B_w + 1, 256>>>(ei, W1, W2, W3, w1, w2, w3,
                                          e, B_deg, B_w);

    // launch 2: chained scan (dinv, rowptr, cursor, count reset)
    scan_chained_kernel<<<nb, 1024>>>(n, nb);

    // launch 3: FUSED csr-fill (src<<8) + x->prescaled-fp16
    const int B_fill = (e + 255) / 256;
    const int B_conv = (n * 16 + 255) / 256;
    convfill_kernel<<<B_fill + B_conv, 256>>>(x, x16, ei, n, e, B_fill);

    // launch 4: agg1 (pure sum) -> a1
    agg16_kernel<F_IN, 0, false, false, false><<<(n + 7) / 8, 128>>>(
        x16, nullptr, a1, nullptr, n);

    // launch 5: FUSED GEMM1+GEMM2 -> g2 (dinv-prescaled)
    gemm12_kernel<<<mt, 256, G12_SMEM>>>(a1, w1, w2, b1, g2);

    // launch 6: agg2 + b2 + relu -> h2
    agg16_kernel<F_H, 0, true, true, false><<<(n + 7) / 8, 128>>>(
        g2, b2, h2, nullptr, n);

    // launch 7: GEMM3 (128->32) * dinv -> g3
    {
        dim3 grid(mt, 1);
        gemm_f16<32, 128, 8, 1, false, false, true><<<grid, 256, smem32>>>(
            h2, w3, nullptr, g3, n, F_OUT);
    }

    // launch 8: agg3 + b3 -> out fp32 (g3 rows are 64B: shift offsets >>2)
    agg16_kernel<F_OUT, 2, true, false, true><<<(n + 31) / 32, 128>>>(
        g3, b3, nullptr, out, n);
}